// round 1
// baseline (speedup 1.0000x reference)
#include <cuda_runtime.h>
#include <math.h>

// ---------------- problem constants ----------------
#define NT       128     // threads per block
#define BT       16      // batch items per block -> 128 blocks
#define T_STEPS  128
#define STATE    115
#define ACT      39
#define CIN      154     // STATE + ACT
#define COUT     116     // STATE + 1 reward channel

#define SBUF 132         // activation buffer stride (>=128, mod 32 = 4)
#define SX   116         // x state stride
#define SA   40          // action stride

// ---------------- shared memory layout (float offsets) ----------------
// W0..W7 at native [fi][fo]; W8 padded to [8][116]; Wr padded to 348; biases; b8 padded to 116
#define OW0   0
#define OW1   2464       // 154*16
#define OW2   2976       // +16*32
#define OW3   5024       // +32*64
#define OW4   13216      // +64*128
#define OW5   21408      // +128*64
#define OW6   23456      // +64*32
#define OW7   23968      // +32*16
#define OW8   24096      // +16*8 ; W8 is 8x116 padded
#define OWR   25024      // +8*116 ; Wr 115*3 padded to 348
#define OB0   25372
#define OB1   25388
#define OB2   25420
#define OB3   25484
#define OB4   25612
#define OB5   25676
#define OB6   25708
#define OB7   25724
#define OB8   25732      // 116 (padded)
#define OBR   25848      // 4
#define OBUFA 25852      // 16*132 = 2112
#define OBUFB 27964      // 2112
#define OXS   30076      // 16*116 = 1856
#define OAB   31932      // 16*40  = 640
#define SMEM_FLOATS 32572
#define SMEM_BYTES  (SMEM_FLOATS * 4)   // 130288 B

struct Params {
    const float* u;
    const float* W[9];
    const float* b[9];
    const float* Wr;
    const float* br;
    float* out;
};

__device__ __forceinline__ void cpy_sh(float* dst, const float* __restrict__ src, int n) {
    for (int k = threadIdx.x; k < n; k += NT) dst[k] = src[k];
}

// Generic register-tiled layer: out[b][o] = act( in[b][:] @ W + bias )
// W: [FI][FO] row-major in SMEM. in/out strides = SBUF. TO in {1,2,4}.
template<int FI, int FO, int TO, int TB, bool CLIP>
__device__ __forceinline__ void layerT(const float* __restrict__ W,
                                       const float* __restrict__ bias,
                                       const float* __restrict__ in,
                                       float* __restrict__ out) {
    constexpr int G = FO / TO;
    constexpr int TILES = G * (BT / TB);
    for (int tile = threadIdx.x; tile < TILES; tile += NT) {
        const int og = tile % G;
        const int bg = tile / G;
        const int o0 = og * TO;
        const float* inp = in + bg * TB * SBUF;
        float acc[TB][TO];
#pragma unroll
        for (int tb = 0; tb < TB; ++tb)
#pragma unroll
            for (int to = 0; to < TO; ++to) acc[tb][to] = bias[o0 + to];
#pragma unroll
        for (int i = 0; i < FI; ++i) {
            float w[TO];
            if constexpr (TO == 4) {
                float4 wv = *(const float4*)(W + i * FO + o0);
                w[0] = wv.x; w[1] = wv.y; w[2] = wv.z; w[3] = wv.w;
            } else if constexpr (TO == 2) {
                float2 wv = *(const float2*)(W + i * FO + o0);
                w[0] = wv.x; w[1] = wv.y;
            } else {
                w[0] = W[i * FO + o0];
            }
#pragma unroll
            for (int tb = 0; tb < TB; ++tb) {
                float v = inp[tb * SBUF + i];
#pragma unroll
                for (int to = 0; to < TO; ++to)
                    acc[tb][to] = fmaf(v, w[to], acc[tb][to]);
            }
        }
#pragma unroll
        for (int tb = 0; tb < TB; ++tb)
#pragma unroll
            for (int to = 0; to < TO; ++to) {
                float r = acc[tb][to];
                if constexpr (CLIP) r = fminf(fmaxf(r, 0.0f), 6.0f);
                out[(bg * TB + tb) * SBUF + o0 + to] = r;
            }
    }
}

__global__ void __launch_bounds__(NT, 1) worldnet_kernel(Params p) {
    extern __shared__ float sh[];
    const int tid = threadIdx.x;
    const int b0 = blockIdx.x * BT;

    // ---- one-time: load all weights/biases into SMEM ----
    cpy_sh(sh + OW0, p.W[0], 154 * 16);
    cpy_sh(sh + OW1, p.W[1], 16 * 32);
    cpy_sh(sh + OW2, p.W[2], 32 * 64);
    cpy_sh(sh + OW3, p.W[3], 64 * 128);
    cpy_sh(sh + OW4, p.W[4], 128 * 64);
    cpy_sh(sh + OW5, p.W[5], 64 * 32);
    cpy_sh(sh + OW6, p.W[6], 32 * 16);
    cpy_sh(sh + OW7, p.W[7], 16 * 8);
    for (int k = tid; k < 8 * 116; k += NT) {           // W8 padded 8x116
        int i = k / 116, o = k - i * 116;
        sh[OW8 + k] = (o < STATE) ? p.W[8][i * STATE + o] : 0.0f;
    }
    for (int k = tid; k < 348; k += NT)                  // Wr padded
        sh[OWR + k] = (k < STATE * 3) ? p.Wr[k] : 0.0f;
    cpy_sh(sh + OB0, p.b[0], 16);
    cpy_sh(sh + OB1, p.b[1], 32);
    cpy_sh(sh + OB2, p.b[2], 64);
    cpy_sh(sh + OB3, p.b[3], 128);
    cpy_sh(sh + OB4, p.b[4], 64);
    cpy_sh(sh + OB5, p.b[5], 32);
    cpy_sh(sh + OB6, p.b[6], 16);
    cpy_sh(sh + OB7, p.b[7], 8);
    for (int k = tid; k < 116; k += NT)
        sh[OB8 + k] = (k < STATE) ? p.b[8][k] : 0.0f;
    for (int k = tid; k < 4; k += NT)
        sh[OBR + k] = (k < 3) ? p.br[k] : 0.0f;

    // ---- init x0 = u[:, 0, :STATE] ----
    for (int k = tid; k < BT * STATE; k += NT) {
        int b = k / STATE, i = k - b * STATE;
        sh[OXS + b * SX + i] = p.u[(size_t)(b0 + b) * T_STEPS * CIN + i];
    }
    __syncthreads();

    // ---- time loop ----
    for (int t = 0; t < T_STEPS; ++t) {
        // stage actions a_t (issue gmem loads first so their latency overlaps the state stores)
        for (int k = tid; k < BT * ACT; k += NT) {
            int b = k / ACT, j = k - b * ACT;
            sh[OAB + b * SA + j] =
                p.u[((size_t)(b0 + b) * T_STEPS + t) * CIN + STATE + j];
        }
        // write out[:, t, 0:STATE] = x_t
        for (int k = tid; k < BT * STATE; k += NT) {
            int b = k / STATE, i = k - b * STATE;
            p.out[((size_t)(b0 + b) * T_STEPS + t) * COUT + i] = sh[OXS + b * SX + i];
        }
        __syncthreads();

        // ---- L0: (115 from x) + (39 from a) -> 16, clip. TO=2, TB=1, 128 tiles ----
        {
            const float* W = sh + OW0;
            const float* bias = sh + OB0;
            for (int tile = tid; tile < 8 * BT; tile += NT) {
                int og = tile & 7, b = tile >> 3;
                int o0 = og * 2;
                float a0 = bias[o0], a1 = bias[o0 + 1];
                const float* xr = sh + OXS + b * SX;
#pragma unroll
                for (int i = 0; i < STATE; ++i) {
                    float v = xr[i];
                    float2 w = *(const float2*)(W + i * 16 + o0);
                    a0 = fmaf(v, w.x, a0); a1 = fmaf(v, w.y, a1);
                }
                const float* ar = sh + OAB + b * SA;
#pragma unroll
                for (int j = 0; j < ACT; ++j) {
                    float v = ar[j];
                    float2 w = *(const float2*)(W + (STATE + j) * 16 + o0);
                    a0 = fmaf(v, w.x, a0); a1 = fmaf(v, w.y, a1);
                }
                a0 = fminf(fmaxf(a0, 0.0f), 6.0f);
                a1 = fminf(fmaxf(a1, 0.0f), 6.0f);
                float* o = sh + OBUFB + b * SBUF + o0;
                o[0] = a0; o[1] = a1;
            }
        }
        __syncthreads();

        layerT<16, 32, 2, 2, true >(sh + OW1, sh + OB1, sh + OBUFB, sh + OBUFA); __syncthreads();
        layerT<32, 64, 4, 2, true >(sh + OW2, sh + OB2, sh + OBUFA, sh + OBUFB); __syncthreads();
        layerT<64, 128, 4, 4, true >(sh + OW3, sh + OB3, sh + OBUFB, sh + OBUFA); __syncthreads();
        layerT<128, 64, 4, 2, true >(sh + OW4, sh + OB4, sh + OBUFA, sh + OBUFB); __syncthreads();
        layerT<64, 32, 2, 2, true >(sh + OW5, sh + OB5, sh + OBUFB, sh + OBUFA); __syncthreads();
        layerT<32, 16, 2, 1, true >(sh + OW6, sh + OB6, sh + OBUFA, sh + OBUFB); __syncthreads();
        layerT<16, 8, 1, 1, true >(sh + OW7, sh + OB7, sh + OBUFB, sh + OBUFA); __syncthreads();
        layerT<8, 116, 4, 2, false>(sh + OW8, sh + OB8, sh + OBUFA, sh + OBUFB); __syncthreads();

        // ---- residual: x <- x + delta ----
        for (int k = tid; k < BT * STATE; k += NT) {
            int b = k / STATE, i = k - b * STATE;
            sh[OXS + b * SX + i] += sh[OBUFB + b * SBUF + i];
        }
        __syncthreads();

        // ---- reward from x_{t+1}: 8 lanes per item ----
        {
            int b = tid >> 3;
            int l = tid & 7;
            float p0 = 0.f, p1 = 0.f, p2 = 0.f;
            const float* xr = sh + OXS + b * SX;
            const float* Wr = sh + OWR;
            for (int i = l; i < STATE; i += 8) {
                float v = xr[i];
                p0 = fmaf(v, Wr[3 * i + 0], p0);
                p1 = fmaf(v, Wr[3 * i + 1], p1);
                p2 = fmaf(v, Wr[3 * i + 2], p2);
            }
#pragma unroll
            for (int off = 4; off > 0; off >>= 1) {
                p0 += __shfl_down_sync(0xffffffffu, p0, off, 8);
                p1 += __shfl_down_sync(0xffffffffu, p1, off, 8);
                p2 += __shfl_down_sync(0xffffffffu, p2, off, 8);
            }
            if (l == 0) {
                p0 += sh[OBR + 0]; p1 += sh[OBR + 1]; p2 += sh[OBR + 2];
                p.out[((size_t)(b0 + b) * T_STEPS + t) * COUT + STATE] =
                    -sqrtf(p0 * p0 + p1 * p1 + p2 * p2);
            }
        }
        // no barrier needed: next iteration only reads OXS / writes OAB & gmem
    }
}

extern "C" void kernel_launch(void* const* d_in, const int* in_sizes, int n_in,
                              void* d_out, int out_size) {
    Params p;
    p.u = (const float*)d_in[0];
    for (int i = 0; i < 9; ++i) {
        p.W[i] = (const float*)d_in[1 + 2 * i];
        p.b[i] = (const float*)d_in[2 + 2 * i];
    }
    p.Wr = (const float*)d_in[19];
    p.br = (const float*)d_in[20];
    p.out = (float*)d_out;

    cudaFuncSetAttribute(worldnet_kernel,
                         cudaFuncAttributeMaxDynamicSharedMemorySize, SMEM_BYTES);
    worldnet_kernel<<<2048 / BT, NT, SMEM_BYTES>>>(p);
}

// round 2
// speedup vs baseline: 1.1165x; 1.1165x over previous
#include <cuda_runtime.h>
#include <math.h>

// ---------------- problem constants ----------------
#define NT       256     // threads per block (8 warps -> 2 per SMSP)
#define BT       16      // batch items per block -> 128 blocks
#define T_STEPS  128
#define STATE    115
#define ACT      39
#define CIN      154     // STATE + ACT
#define COUT     116     // STATE + 1 reward channel

#define SBUF 132         // activation buffer stride
#define SX   116         // x state stride
#define SA   40          // action stride

// ---------------- shared memory layout (float offsets) ----------------
#define OW0   0
#define OW1   2464       // 154*16
#define OW2   2976       // +16*32
#define OW3   5024       // +32*64
#define OW4   13216      // +64*128
#define OW5   21408      // +128*64
#define OW6   23456      // +64*32
#define OW7   23968      // +32*16
#define OW8   24096      // +16*8 ; W8 is 8x116 padded
#define OWR   25024      // Wr padded to 348
#define OB0   25372
#define OB1   25388
#define OB2   25420
#define OB3   25484
#define OB4   25612
#define OB5   25676
#define OB6   25708
#define OB7   25724
#define OB8   25732      // 116 (padded)
#define OBR   25848      // 4
#define OBUFA 25852      // 16*132 = 2112
#define OBUFB 27964      // 2112
#define OXS   30076      // 16*116 = 1856
#define OAB   31932      // 16*40  = 640
#define SMEM_FLOATS 32572
#define SMEM_BYTES  (SMEM_FLOATS * 4)   // 130288 B

struct Params {
    const float* u;
    const float* W[9];
    const float* b[9];
    const float* Wr;
    const float* br;
    float* out;
};

__device__ __forceinline__ void cpy_sh(float* dst, const float* __restrict__ src, int n) {
    for (int k = threadIdx.x; k < n; k += NT) dst[k] = src[k];
}

// Generic register-tiled layer: out[b][o] = act( in[b][:] @ W + bias )
// W: [FI][FO] row-major in SMEM. in/out strides = SBUF. TO in {1,2,4}.
template<int FI, int FO, int TO, int TB, bool CLIP>
__device__ __forceinline__ void layerT(const float* __restrict__ W,
                                       const float* __restrict__ bias,
                                       const float* __restrict__ in,
                                       float* __restrict__ out) {
    constexpr int G = FO / TO;
    constexpr int TILES = G * (BT / TB);
    for (int tile = threadIdx.x; tile < TILES; tile += NT) {
        const int og = tile % G;
        const int bg = tile / G;
        const int o0 = og * TO;
        const float* inp = in + bg * TB * SBUF;
        float acc[TB][TO];
#pragma unroll
        for (int tb = 0; tb < TB; ++tb)
#pragma unroll
            for (int to = 0; to < TO; ++to) acc[tb][to] = bias[o0 + to];
#pragma unroll
        for (int i = 0; i < FI; ++i) {
            float w[TO];
            if constexpr (TO == 4) {
                float4 wv = *(const float4*)(W + i * FO + o0);
                w[0] = wv.x; w[1] = wv.y; w[2] = wv.z; w[3] = wv.w;
            } else if constexpr (TO == 2) {
                float2 wv = *(const float2*)(W + i * FO + o0);
                w[0] = wv.x; w[1] = wv.y;
            } else {
                w[0] = W[i * FO + o0];
            }
#pragma unroll
            for (int tb = 0; tb < TB; ++tb) {
                float v = inp[tb * SBUF + i];
#pragma unroll
                for (int to = 0; to < TO; ++to)
                    acc[tb][to] = fmaf(v, w[to], acc[tb][to]);
            }
        }
#pragma unroll
        for (int tb = 0; tb < TB; ++tb)
#pragma unroll
            for (int to = 0; to < TO; ++to) {
                float r = acc[tb][to];
                if constexpr (CLIP) r = fminf(fmaxf(r, 0.0f), 6.0f);
                out[(bg * TB + tb) * SBUF + o0 + to] = r;
            }
    }
}

__global__ void __launch_bounds__(NT, 1) worldnet_kernel(Params p) {
    extern __shared__ float sh[];
    const int tid = threadIdx.x;
    const int b0 = blockIdx.x * BT;

    // ---- one-time: load all weights/biases into SMEM ----
    cpy_sh(sh + OW0, p.W[0], 154 * 16);
    cpy_sh(sh + OW1, p.W[1], 16 * 32);
    cpy_sh(sh + OW2, p.W[2], 32 * 64);
    cpy_sh(sh + OW3, p.W[3], 64 * 128);
    cpy_sh(sh + OW4, p.W[4], 128 * 64);
    cpy_sh(sh + OW5, p.W[5], 64 * 32);
    cpy_sh(sh + OW6, p.W[6], 32 * 16);
    cpy_sh(sh + OW7, p.W[7], 16 * 8);
    for (int k = tid; k < 8 * 116; k += NT) {           // W8 padded 8x116
        int i = k / 116, o = k - i * 116;
        sh[OW8 + k] = (o < STATE) ? p.W[8][i * STATE + o] : 0.0f;
    }
    for (int k = tid; k < 348; k += NT)                  // Wr padded
        sh[OWR + k] = (k < STATE * 3) ? p.Wr[k] : 0.0f;
    cpy_sh(sh + OB0, p.b[0], 16);
    cpy_sh(sh + OB1, p.b[1], 32);
    cpy_sh(sh + OB2, p.b[2], 64);
    cpy_sh(sh + OB3, p.b[3], 128);
    cpy_sh(sh + OB4, p.b[4], 64);
    cpy_sh(sh + OB5, p.b[5], 32);
    cpy_sh(sh + OB6, p.b[6], 16);
    cpy_sh(sh + OB7, p.b[7], 8);
    for (int k = tid; k < 116; k += NT)
        sh[OB8 + k] = (k < STATE) ? p.b[8][k] : 0.0f;
    for (int k = tid; k < 4; k += NT)
        sh[OBR + k] = (k < 3) ? p.br[k] : 0.0f;

    // ---- init x0 = u[:, 0, :STATE] ----
    for (int k = tid; k < BT * STATE; k += NT) {
        int b = k / STATE, i = k - b * STATE;
        sh[OXS + b * SX + i] = p.u[(size_t)(b0 + b) * T_STEPS * CIN + i];
    }
    __syncthreads();

    // ---- time loop ----
    for (int t = 0; t < T_STEPS; ++t) {
        // stage actions a_t (gmem loads issued first to overlap with the stores)
        for (int k = tid; k < BT * ACT; k += NT) {
            int b = k / ACT, j = k - b * ACT;
            sh[OAB + b * SA + j] =
                p.u[((size_t)(b0 + b) * T_STEPS + t) * CIN + STATE + j];
        }
        // write out[:, t, 0:STATE] = x_t
        for (int k = tid; k < BT * STATE; k += NT) {
            int b = k / STATE, i = k - b * STATE;
            p.out[((size_t)(b0 + b) * T_STEPS + t) * COUT + i] = sh[OXS + b * SX + i];
        }
        __syncthreads();

        // ---- L0: concat(x,a)[154] -> 16, clip. TO=1 -> 256 tiles ----
        {
            const float* W = sh + OW0;
            const float* bias = sh + OB0;
            const int og = tid & 15;       // output neuron
            const int b  = tid >> 4;       // batch item
            float a0 = bias[og];
            const float* xr = sh + OXS + b * SX;
#pragma unroll
            for (int i = 0; i < STATE; ++i)
                a0 = fmaf(xr[i], W[i * 16 + og], a0);
            const float* ar = sh + OAB + b * SA;
#pragma unroll
            for (int j = 0; j < ACT; ++j)
                a0 = fmaf(ar[j], W[(STATE + j) * 16 + og], a0);
            a0 = fminf(fmaxf(a0, 0.0f), 6.0f);
            sh[OBUFB + b * SBUF + og] = a0;
        }
        __syncthreads();

        layerT<16, 32, 2, 1, true >(sh + OW1, sh + OB1, sh + OBUFB, sh + OBUFA); __syncthreads();
        layerT<32, 64, 4, 1, true >(sh + OW2, sh + OB2, sh + OBUFA, sh + OBUFB); __syncthreads();
        layerT<64, 128, 4, 2, true >(sh + OW3, sh + OB3, sh + OBUFB, sh + OBUFA); __syncthreads();
        layerT<128, 64, 4, 1, true >(sh + OW4, sh + OB4, sh + OBUFA, sh + OBUFB); __syncthreads();
        layerT<64, 32, 2, 1, true >(sh + OW5, sh + OB5, sh + OBUFB, sh + OBUFA); __syncthreads();
        layerT<32, 16, 1, 1, true >(sh + OW6, sh + OB6, sh + OBUFA, sh + OBUFB); __syncthreads();
        layerT<16, 8, 1, 1, true >(sh + OW7, sh + OB7, sh + OBUFB, sh + OBUFA); __syncthreads();
        layerT<8, 116, 4, 1, false>(sh + OW8, sh + OB8, sh + OBUFA, sh + OBUFB); __syncthreads();

        // ---- residual: x <- x + delta ----
        for (int k = tid; k < BT * STATE; k += NT) {
            int b = k / STATE, i = k - b * STATE;
            sh[OXS + b * SX + i] += sh[OBUFB + b * SBUF + i];
        }
        __syncthreads();

        // ---- reward from x_{t+1}: 16 lanes per item ----
        {
            int b = tid >> 4;
            int l = tid & 15;
            float p0 = 0.f, p1 = 0.f, p2 = 0.f;
            const float* xr = sh + OXS + b * SX;
            const float* Wr = sh + OWR;
#pragma unroll
            for (int i = l; i < STATE; i += 16) {
                float v = xr[i];
                p0 = fmaf(v, Wr[3 * i + 0], p0);
                p1 = fmaf(v, Wr[3 * i + 1], p1);
                p2 = fmaf(v, Wr[3 * i + 2], p2);
            }
#pragma unroll
            for (int off = 8; off > 0; off >>= 1) {
                p0 += __shfl_down_sync(0xffffffffu, p0, off, 16);
                p1 += __shfl_down_sync(0xffffffffu, p1, off, 16);
                p2 += __shfl_down_sync(0xffffffffu, p2, off, 16);
            }
            if (l == 0) {
                p0 += sh[OBR + 0]; p1 += sh[OBR + 1]; p2 += sh[OBR + 2];
                p.out[((size_t)(b0 + b) * T_STEPS + t) * COUT + STATE] =
                    -sqrtf(p0 * p0 + p1 * p1 + p2 * p2);
            }
        }
        // no barrier needed: next iteration only reads OXS / writes OAB & gmem
    }
}

extern "C" void kernel_launch(void* const* d_in, const int* in_sizes, int n_in,
                              void* d_out, int out_size) {
    Params p;
    p.u = (const float*)d_in[0];
    for (int i = 0; i < 9; ++i) {
        p.W[i] = (const float*)d_in[1 + 2 * i];
        p.b[i] = (const float*)d_in[2 + 2 * i];
    }
    p.Wr = (const float*)d_in[19];
    p.br = (const float*)d_in[20];
    p.out = (float*)d_out;

    cudaFuncSetAttribute(worldnet_kernel,
                         cudaFuncAttributeMaxDynamicSharedMemorySize, SMEM_BYTES);
    worldnet_kernel<<<2048 / BT, NT, SMEM_BYTES>>>(p);
}